// round 12
// baseline (speedup 1.0000x reference)
#include <cuda_runtime.h>

#define NNODE 8000
#define TDIM 12
#define NBLK 125
#define NPB 64        // nodes per block (125*64 = 8000); 125 blocks <= 148 SMs => 1 wave
#define XROW 61       // padded x smem row stride (odd => conflict-free column reads)

typedef unsigned long long u64t;

// Scratch (device globals; no allocation allowed). Zero-init; self-resetting.
__device__ float g_partial[NBLK][120];  // [b][0:60)=lhs1 (t*5+f), [60:120)=M (f*12+t')
__device__ unsigned int g_arrive;
__device__ unsigned int g_done;

// ---- f32x2 packed math helpers (sm_103a; PTX-only) ----
__device__ __forceinline__ u64t pack2(float lo, float hi) {
    u64t d; asm("mov.b64 %0,{%1,%2};" : "=l"(d) : "f"(lo), "f"(hi)); return d;
}
__device__ __forceinline__ u64t fma2(u64t a, u64t b, u64t c) {
    u64t d; asm("fma.rn.f32x2 %0,%1,%2,%3;" : "=l"(d) : "l"(a), "l"(b), "l"(c));
    return d;
}
__device__ __forceinline__ void unpack2(u64t v, float& lo, float& hi) {
    asm("mov.b64 {%0,%1},%2;" : "=f"(lo), "=f"(hi) : "l"(v));
}

// ---- conv quarter: outputs t = 3H..3H+2 for one node ----
template <int H>
__device__ __forceinline__ void node_quarter(
    const float* __restrict__ xrow, const float* __restrict__ sA,
    const float* __restrict__ sw, const float* __restrict__ sb,
    int n, float* __restrict__ out)
{
    constexpr int TLO = (H == 0) ? 0 : (H == 1) ? 2 : (H == 2) ? 4 : 8;
    constexpr int W   = (H == 0 || H == 3) ? 4 : 6;
    constexpr int P   = W / 2;

    u64t x2p[5][P];
#pragma unroll
    for (int f = 0; f < 5; f++)
#pragma unroll
        for (int j = 0; j < P; j++) x2p[f][j] = 0ull;

#pragma unroll
    for (int tp = 0; tp < 12; tp++) {
        u64t a2[P];
        const u64t* ap = (const u64t*)(sA + tp * 12 + TLO);
#pragma unroll
        for (int j = 0; j < P; j++) a2[j] = ap[j];
#pragma unroll
        for (int f = 0; f < 5; f++) {
            const float xv = xrow[tp * 5 + f];
            const u64t xvv = pack2(xv, xv);
#pragma unroll
            for (int j = 0; j < P; j++) x2p[f][j] = fma2(xvv, a2[j], x2p[f][j]);
        }
    }

    float x2[5][W];
#pragma unroll
    for (int f = 0; f < 5; f++)
#pragma unroll
        for (int j = 0; j < P; j++) unpack2(x2p[f][j], x2[f][2 * j], x2[f][2 * j + 1]);

#pragma unroll
    for (int o = 0; o < 5; o++) {
        float wr[15];
#pragma unroll
        for (int q = 0; q < 15; q++) wr[q] = sw[o * 15 + q];
        float* op = out + (size_t)o * NNODE * TDIM + (size_t)n * TDIM + 3 * H;
#pragma unroll
        for (int u = 0; u < 3; u++) {
            const int t = 3 * H + u;
            const int k = t - TLO;
            float acc = sb[o];
#pragma unroll
            for (int i = 0; i < 5; i++) {
                if (t > 0)  acc += wr[i * 3 + 0] * x2[i][k - 1];
                acc += wr[i * 3 + 1] * x2[i][k];
                if (t < 11) acc += wr[i * 3 + 2] * x2[i][k + 1];
            }
            op[u] = acc;
        }
    }
}

// ===========================================================================
// Single fused kernel, one co-resident wave:
//  phase 1: per-block partials -> g_partial, counter arrive
//  barrier: poll counter (volatile L2 read + nanosleep backoff)
//  phase 2: EVERY block redundantly finishes reduction + attention (parallel)
//  phase 3: conv on the smem-resident x tile, 4 threads/node
// ===========================================================================
__global__ void __launch_bounds__(256) k_fused(
    const float* __restrict__ x, const float* __restrict__ U1,
    const float* __restrict__ U2, const float* __restrict__ U3,
    const float* __restrict__ be, const float* __restrict__ Ve,
    const float* __restrict__ w2, const float* __restrict__ b2,
    float* __restrict__ out)
{
    __shared__ float xs[NPB * XROW];
    __shared__ __align__(8) float rhss[12 * NPB];   // [t'][n]
    __shared__ __align__(8) float u1s[NPB];
    __shared__ __align__(8) float u2s[5 * NPB];     // [f][n]
    __shared__ float sred[240];
    __shared__ __align__(16) float sA[144];
    __shared__ float sw[75], sb[5];
    __shared__ float lhs[60], Mm[60], S[144], E[144];

    const int tid = threadIdx.x;
    const int blk = blockIdx.x;
    const int n0 = blk * NPB;

    // ---- prologue: x tile + params (coalesced) ----
    const float4* gx4 = (const float4*)(x + (size_t)n0 * 60);
#pragma unroll
    for (int q = tid; q < NPB * 15; q += 256) {
        float4 v = gx4[q];
        const int e = q * 4;
        float* d = &xs[(e / 60) * XROW + (e % 60)];
        d[0] = v.x; d[1] = v.y; d[2] = v.z; d[3] = v.w;
    }
    if (tid < NPB) u1s[tid] = U1[n0 + tid];
#pragma unroll
    for (int i = tid; i < 5 * NPB; i += 256)           // 320 > 256: stride!
        u2s[i] = U2[(i >> 6) * NNODE + n0 + (i & 63)];
    if (tid < 75) sw[tid] = w2[tid];
    if (tid < 5)  sb[tid] = b2[tid];
    float myVe[12], be_v = 0.f;
    if (tid < 144) {
        be_v = be[tid];
        const int i = tid / 12;
#pragma unroll
        for (int k = 0; k < 12; k++) myVe[k] = Ve[i * 12 + k];
    }
    float u3[5];
#pragma unroll
    for (int f = 0; f < 5; f++) u3[f] = U3[f];
    __syncthreads();

    // ---- rhs[t'][n] = sum_g U3[g]*x[n,t',g] ----
#pragma unroll
    for (int idx = tid; idx < 12 * NPB; idx += 256) {
        const int t = idx >> 6, n = idx & 63;
        const float* xr = &xs[n * XROW + t * 5];
        float s = 0.f;
#pragma unroll
        for (int f = 0; f < 5; f++) s += u3[f] * xr[f];
        rhss[t * NPB + n] = s;
    }
    __syncthreads();

    // ---- per-component partials: 2 threads/component over 32-node halves ----
    if (tid < 240) {
        const int c = tid % 120, h = tid / 120;
        const int nlo = h * 32;
        float s;
        if (c < 60) {
            s = 0.f;
#pragma unroll 8
            for (int n = nlo; n < nlo + 32; n++) s += u1s[n] * xs[n * XROW + c];
        } else {
            const int f = (c - 60) / 12, t = (c - 60) % 12;
            const u64t* up = (const u64t*)(u2s + f * NPB + nlo);
            const u64t* rp = (const u64t*)(rhss + t * NPB + nlo);
            u64t acc = 0ull;
#pragma unroll
            for (int j = 0; j < 16; j++) acc = fma2(up[j], rp[j], acc);
            float lo, hi; unpack2(acc, lo, hi);
            s = lo + hi;
        }
        sred[tid] = s;
    }
    __syncthreads();
    if (tid < 120) {
        g_partial[blk][tid] = sred[tid] + sred[tid + 120];
        __threadfence();                       // writers fence their stores
    }
    __syncthreads();

    // ---- grid barrier: arrive, then poll (all 125 blocks co-resident) ----
    if (tid == 0) {
        atomicAdd(&g_arrive, 1u);
        const volatile unsigned int* pa = (const volatile unsigned int*)&g_arrive;
        while (*pa < (unsigned)NBLK) __nanosleep(32);
    }
    __syncthreads();
    __threadfence();                           // acquire all blocks' partials

    // ---- finish 125-way reduction (2 threads/component, parallel per block) ----
    if (tid < 240) {
        const int c = tid % 120, h = tid / 120;
        const int blo = h ? 63 : 0, bhi = h ? 125 : 63;
        float s = 0.f;
#pragma unroll 7
        for (int b = blo; b < bhi; b++) s += g_partial[b][c];
        sred[tid] = s;
    }
    __syncthreads();
    if (tid < 120) {
        const float s = sred[tid] + sred[tid + 120];
        if (tid < 60) lhs[tid] = s;
        else          Mm[tid - 60] = s;
    }
    __syncthreads();

    // ---- attention (redundant per block, deterministic) ----
    if (tid < 144) {
        const int i = tid / 12, c = tid % 12;
        float p = 0.f;
#pragma unroll
        for (int f = 0; f < 5; f++) p += lhs[i * 5 + f] * Mm[f * 12 + c];
        p += be_v;
        S[tid] = 1.f / (1.f + expf(-p));
    }
    __syncthreads();
    if (tid < 144) {
        const int c = tid % 12;
        float e = 0.f;
#pragma unroll
        for (int k = 0; k < 12; k++) e += myVe[k] * S[k * 12 + c];
        E[tid] = e;
    }
    __syncthreads();
    if (tid < 144) {
        const int c = tid % 12;
        float mx = -1e30f;
#pragma unroll
        for (int k = 0; k < 12; k++) mx = fmaxf(mx, E[k * 12 + c]);
        float sum = 0.f;
#pragma unroll
        for (int k = 0; k < 12; k++) sum += expf(E[k * 12 + c] - mx);
        sA[tid] = expf(E[tid] - mx) / sum;
    }
    __syncthreads();

    // ---- conv: 4 threads/node on smem-resident tile ----
    {
        const int nl = tid >> 2;
        const int h = tid & 3;
        const int n = n0 + nl;
        const float* xrow = &xs[nl * XROW];
        switch (h) {
            case 0: node_quarter<0>(xrow, sA, sw, sb, n, out); break;
            case 1: node_quarter<1>(xrow, sA, sw, sb, n, out); break;
            case 2: node_quarter<2>(xrow, sA, sw, sb, n, out); break;
            default: node_quarter<3>(xrow, sA, sw, sb, n, out); break;
        }
    }

    // ---- self-reset for next graph replay (R4-proven pattern) ----
    if (tid == 0) {
        const unsigned int d = atomicAdd(&g_done, 1u);
        if (d == (unsigned)(NBLK - 1)) {
            g_arrive = 0u;
            g_done = 0u;
            __threadfence();
        }
    }
}

extern "C" void kernel_launch(void* const* d_in, const int* in_sizes, int n_in,
                              void* d_out, int out_size)
{
    // metadata order: x, adj, U1_1, U2_1, U3_1, be_1, Ve_1,
    //                 U1_2, U2_2, U3_2, be_2, Ve_2,
    //                 conv1_w, conv1_b, conv2_w, conv2_b, W_hgc, b_hgc
    const float* x  = (const float*)d_in[0];
    const float* U1 = (const float*)d_in[7];
    const float* U2 = (const float*)d_in[8];
    const float* U3 = (const float*)d_in[9];
    const float* be = (const float*)d_in[10];
    const float* Ve = (const float*)d_in[11];
    const float* w2 = (const float*)d_in[14];
    const float* b2 = (const float*)d_in[15];
    float* out = (float*)d_out;

    k_fused<<<NBLK, 256>>>(x, U1, U2, U3, be, Ve, w2, b2, out);
}

// round 13
// speedup vs baseline: 1.1429x; 1.1429x over previous
#include <cuda_runtime.h>

#define NNODE 8000
#define TDIM 12
#define NBLK 100
#define NPB 80        // nodes per block (100*80 = 8000); 100 <= 148 SMs => 1 wave
#define NT 512
#define XROW 61       // padded smem row stride (odd => conflict-free column reads)

typedef unsigned long long u64t;

// Scratch (device globals; no allocation allowed). Zero-init; self-resetting.
__device__ float g_partial[NBLK][120];  // [b][0:60)=lhs1 (t*5+f), [60:120)=M (f*12+t')
__device__ unsigned int g_arrive;
__device__ unsigned int g_done;

// ---- f32x2 packed math helpers (sm_103a; PTX-only) ----
__device__ __forceinline__ u64t pack2(float lo, float hi) {
    u64t d; asm("mov.b64 %0,{%1,%2};" : "=l"(d) : "f"(lo), "f"(hi)); return d;
}
__device__ __forceinline__ u64t fma2(u64t a, u64t b, u64t c) {
    u64t d; asm("fma.rn.f32x2 %0,%1,%2,%3;" : "=l"(d) : "l"(a), "l"(b), "l"(c));
    return d;
}
__device__ __forceinline__ void unpack2(u64t v, float& lo, float& hi) {
    asm("mov.b64 {%0,%1},%2;" : "=f"(lo), "=f"(hi) : "l"(v));
}

// ===========================================================================
// Single fused kernel, one co-resident wave, 512 threads/block:
//  phase 1: per-block partials (4 threads/component) -> g_partial, arrive
//  barrier: poll counter (volatile L2 read + nanosleep backoff)
//  phase 2: EVERY block redundantly finishes reduction (4 thr/comp) + attention
//  phase 3a: x2[n][f][t] = sum_tp x[n,tp,f]*At2[tp][t]   (1 thread per (n,f))
//  phase 3b: 1x3 conv from smem x2, 1 thread per (n,o), 3x STG.128
// ===========================================================================
__global__ void __launch_bounds__(NT) k_fused(
    const float* __restrict__ x, const float* __restrict__ U1,
    const float* __restrict__ U2, const float* __restrict__ U3,
    const float* __restrict__ be, const float* __restrict__ Ve,
    const float* __restrict__ w2, const float* __restrict__ b2,
    float* __restrict__ out)
{
    __shared__ float xs[NPB * XROW];                // x tile [n][j]
    __shared__ __align__(8) float x2s[NPB * XROW];  // x2 [n][f*12+t]
    __shared__ __align__(8) float rhss[12 * NPB];   // [t'][n]
    __shared__ __align__(8) float u1s[NPB];
    __shared__ __align__(8) float u2s[5 * NPB];     // [f][n]
    __shared__ float sred[480];
    __shared__ __align__(16) float sA[144];
    __shared__ float sw[75], sb[5];
    __shared__ float lhs[60], Mm[60], S[144], E[144];

    const int tid = threadIdx.x;
    const int blk = blockIdx.x;
    const int n0 = blk * NPB;

    // ---- prologue: x tile + params (coalesced) ----
    const float4* gx4 = (const float4*)(x + (size_t)n0 * 60);
#pragma unroll
    for (int q = tid; q < NPB * 15; q += NT) {
        float4 v = gx4[q];
        const int e = q * 4;
        float* d = &xs[(e / 60) * XROW + (e % 60)];
        d[0] = v.x; d[1] = v.y; d[2] = v.z; d[3] = v.w;
    }
    if (tid < NPB) u1s[tid] = U1[n0 + tid];
    if (tid < 5 * NPB)                             // 400 < 512: one-shot OK
        u2s[tid] = U2[(tid / NPB) * NNODE + n0 + (tid % NPB)];
    if (tid < 75) sw[tid] = w2[tid];
    if (tid < 5)  sb[tid] = b2[tid];
    float myVe[12], be_v = 0.f;
    if (tid < 144) {
        be_v = be[tid];
        const int i = tid / 12;
#pragma unroll
        for (int k = 0; k < 12; k++) myVe[k] = Ve[i * 12 + k];
    }
    float u3[5];
#pragma unroll
    for (int f = 0; f < 5; f++) u3[f] = U3[f];
    __syncthreads();

    // ---- rhs[t'][n] = sum_g U3[g]*x[n,t',g] ----
#pragma unroll
    for (int idx = tid; idx < 12 * NPB; idx += NT) {
        const int t = idx / NPB, n = idx % NPB;
        const float* xr = &xs[n * XROW + t * 5];
        float s = 0.f;
#pragma unroll
        for (int f = 0; f < 5; f++) s += u3[f] * xr[f];
        rhss[t * NPB + n] = s;
    }
    __syncthreads();

    // ---- per-component partials: 4 threads/component over 20-node slices ----
    if (tid < 480) {
        const int c = tid % 120, h = tid / 120;
        const int nlo = h * 20;
        float s;
        if (c < 60) {
            s = 0.f;
#pragma unroll 5
            for (int n = nlo; n < nlo + 20; n++) s += u1s[n] * xs[n * XROW + c];
        } else {
            const int f = (c - 60) / 12, t = (c - 60) % 12;
            const u64t* up = (const u64t*)(u2s + f * NPB + nlo);
            const u64t* rp = (const u64t*)(rhss + t * NPB + nlo);
            u64t acc = 0ull;
#pragma unroll
            for (int j = 0; j < 10; j++) acc = fma2(up[j], rp[j], acc);
            float lo, hi; unpack2(acc, lo, hi);
            s = lo + hi;
        }
        sred[tid] = s;
    }
    __syncthreads();
    if (tid < 120) {
        g_partial[blk][tid] = sred[tid] + sred[tid + 120]
                            + sred[tid + 240] + sred[tid + 360];
        __threadfence();                       // writers fence their stores
    }
    __syncthreads();

    // ---- grid barrier: arrive, then poll (all 100 blocks co-resident) ----
    if (tid == 0) {
        atomicAdd(&g_arrive, 1u);
        const volatile unsigned int* pa = (const volatile unsigned int*)&g_arrive;
        while (*pa < (unsigned)NBLK) __nanosleep(32);
    }
    __syncthreads();
    __threadfence();                           // acquire all blocks' partials

    // ---- finish 100-way reduction (4 threads/component, parallel per block) ----
    if (tid < 480) {
        const int c = tid % 120, h = tid / 120;
        float s = 0.f;
#pragma unroll 5
        for (int b = h * 25; b < h * 25 + 25; b++) s += g_partial[b][c];
        sred[tid] = s;
    }
    __syncthreads();
    if (tid < 120) {
        const float s = sred[tid] + sred[tid + 120]
                      + sred[tid + 240] + sred[tid + 360];
        if (tid < 60) lhs[tid] = s;
        else          Mm[tid - 60] = s;
    }
    __syncthreads();

    // ---- attention (redundant per block, deterministic) ----
    if (tid < 144) {
        const int i = tid / 12, c = tid % 12;
        float p = 0.f;
#pragma unroll
        for (int f = 0; f < 5; f++) p += lhs[i * 5 + f] * Mm[f * 12 + c];
        p += be_v;
        S[tid] = 1.f / (1.f + expf(-p));
    }
    __syncthreads();
    if (tid < 144) {
        const int c = tid % 12;
        float e = 0.f;
#pragma unroll
        for (int k = 0; k < 12; k++) e += myVe[k] * S[k * 12 + c];
        E[tid] = e;
    }
    __syncthreads();
    if (tid < 144) {
        const int c = tid % 12;
        float mx = -1e30f;
#pragma unroll
        for (int k = 0; k < 12; k++) mx = fmaxf(mx, E[k * 12 + c]);
        float sum = 0.f;
#pragma unroll
        for (int k = 0; k < 12; k++) sum += expf(E[k * 12 + c] - mx);
        sA[tid] = expf(E[tid] - mx) / sum;
    }
    __syncthreads();

    // ---- phase 3a: x2 rows, 1 thread per (node, f) ----
    if (tid < 5 * NPB) {
        const int n = tid / 5, f = tid % 5;
        const float* xr = &xs[n * XROW + f];
        u64t acc[6];
#pragma unroll
        for (int j = 0; j < 6; j++) acc[j] = 0ull;
#pragma unroll
        for (int tp = 0; tp < 12; tp++) {
            const float xv = xr[tp * 5];
            const u64t xvv = pack2(xv, xv);
            const u64t* ap = (const u64t*)(sA + tp * 12);
#pragma unroll
            for (int j = 0; j < 6; j++) acc[j] = fma2(xvv, ap[j], acc[j]);
        }
        float* dst = &x2s[n * XROW + f * 12];
#pragma unroll
        for (int j = 0; j < 6; j++) unpack2(acc[j], dst[2 * j], dst[2 * j + 1]);
    }
    __syncthreads();

    // ---- phase 3b: conv, 1 thread per (node, o), 3x STG.128 ----
    if (tid < 5 * NPB) {
        const int n = tid / 5, o = tid % 5;
        float wr[15];
#pragma unroll
        for (int q = 0; q < 15; q++) wr[q] = sw[o * 15 + q];
        float y[12];
        const float bo = sb[o];
#pragma unroll
        for (int t = 0; t < 12; t++) y[t] = bo;
        const float* xrow = &x2s[n * XROW];
#pragma unroll
        for (int i = 0; i < 5; i++) {
            float xv[12];
#pragma unroll
            for (int t = 0; t < 12; t++) xv[t] = xrow[i * 12 + t];
            const float w0 = wr[i * 3 + 0], w1 = wr[i * 3 + 1], w2v = wr[i * 3 + 2];
#pragma unroll
            for (int t = 0; t < 12; t++) {
                float acc = w1 * xv[t];
                if (t > 0)  acc += w0 * xv[t - 1];
                if (t < 11) acc += w2v * xv[t + 1];
                y[t] += acc;
            }
        }
        float4* op = (float4*)(out + (size_t)o * NNODE * TDIM + (size_t)(n0 + n) * TDIM);
        op[0] = make_float4(y[0], y[1], y[2],  y[3]);
        op[1] = make_float4(y[4], y[5], y[6],  y[7]);
        op[2] = make_float4(y[8], y[9], y[10], y[11]);
    }

    // ---- self-reset for next graph replay ----
    if (tid == 0) {
        const unsigned int d = atomicAdd(&g_done, 1u);
        if (d == (unsigned)(NBLK - 1)) {
            g_arrive = 0u;
            g_done = 0u;
            __threadfence();
        }
    }
}

extern "C" void kernel_launch(void* const* d_in, const int* in_sizes, int n_in,
                              void* d_out, int out_size)
{
    // metadata order: x, adj, U1_1, U2_1, U3_1, be_1, Ve_1,
    //                 U1_2, U2_2, U3_2, be_2, Ve_2,
    //                 conv1_w, conv1_b, conv2_w, conv2_b, W_hgc, b_hgc
    const float* x  = (const float*)d_in[0];
    const float* U1 = (const float*)d_in[7];
    const float* U2 = (const float*)d_in[8];
    const float* U3 = (const float*)d_in[9];
    const float* be = (const float*)d_in[10];
    const float* Ve = (const float*)d_in[11];
    const float* w2 = (const float*)d_in[14];
    const float* b2 = (const float*)d_in[15];
    float* out = (float*)d_out;

    k_fused<<<NBLK, NT>>>(x, U1, U2, U3, be, Ve, w2, b2, out);
}